// round 10
// baseline (speedup 1.0000x reference)
#include <cuda_runtime.h>
#include <cuda_fp16.h>
#include <cstdint>

#define B_    512
#define T1_   128
#define IN1_  64
#define H1_   256
#define IN3_  32
#define H3_   128
#define T3_   64
#define FCIN_ 3872
#define FEATC 3840

typedef unsigned long long u64;
typedef unsigned int u32;

// ---------------- device scratch ----------------
__device__ __align__(16) __half g_W1h[320 * 1024];   // [k][n], n=gate*256+j, pitch 2048B
__device__ __align__(16) __half g_W2h[320 * 1024];
__device__ __align__(16) float4 g_b1v4[H1_];         // (bi,bf,bg,bo) per j
__device__ __align__(16) float4 g_b2v4[H1_];
__device__ __align__(16) float  g_b3[H3_ * 4];       // [j][(bi,bf,bg,bo)]
__device__ float g_feat[B_ * FEATC];

// ---------------- scalar helpers ----------------
__device__ __forceinline__ float tapx(float x) {           // HW tanh (MUFU)
    float y; asm("tanh.approx.f32 %0, %1;" : "=f"(y) : "f"(x)); return y;
}
__device__ __forceinline__ float sga(float x) {            // sigmoid via tanh
    return fmaf(tapx(0.5f * x), 0.5f, 0.5f);
}
__device__ __forceinline__ u32 smem_u32(const void* p) {
    u32 a;
    asm("{ .reg .u64 t; cvta.to.shared.u64 t, %1; cvt.u32.u64 %0, t; }" : "=r"(a) : "l"(p));
    return a;
}

// ---------------- mma.sync / ldmatrix / cp.async ----------------
__device__ __forceinline__ void ldsm_x4(u32& r0, u32& r1, u32& r2, u32& r3, u32 addr) {
    asm volatile("ldmatrix.sync.aligned.m8n8.x4.shared.b16 {%0,%1,%2,%3}, [%4];"
                 : "=r"(r0), "=r"(r1), "=r"(r2), "=r"(r3) : "r"(addr));
}
// x4 trans: {r0,r1} = B-frag of n-tile at n_off, {r2,r3} = n-tile at n_off+8.
__device__ __forceinline__ void ldsm_x4t(u32& r0, u32& r1, u32& r2, u32& r3, u32 addr) {
    asm volatile("ldmatrix.sync.aligned.m8n8.x4.trans.shared.b16 {%0,%1,%2,%3}, [%4];"
                 : "=r"(r0), "=r"(r1), "=r"(r2), "=r"(r3) : "r"(addr));
}
__device__ __forceinline__ void mma16816(float* c, u32 a0, u32 a1, u32 a2, u32 a3,
                                         u32 b0, u32 b1) {
    asm volatile("mma.sync.aligned.m16n8k16.row.col.f32.f16.f16.f32 "
                 "{%0,%1,%2,%3}, {%4,%5,%6,%7}, {%8,%9}, {%0,%1,%2,%3};"
                 : "+f"(c[0]), "+f"(c[1]), "+f"(c[2]), "+f"(c[3])
                 : "r"(a0), "r"(a1), "r"(a2), "r"(a3), "r"(b0), "r"(b1));
}
__device__ __forceinline__ void cp16(u32 saddr, const void* gptr) {
    asm volatile("cp.async.cg.shared.global [%0], [%1], 16;" :: "r"(saddr), "l"(gptr));
}
__device__ __forceinline__ void cp_commit() {
    asm volatile("cp.async.commit_group;" ::: "memory");
}
template<int N> __device__ __forceinline__ void cp_wait() {
    asm volatile("cp.async.wait_group %0;" :: "n"(N) : "memory");
}

// ---------------- roleB (lstm3) smem layout ----------------
#define ASTRIDE 336
#define BSTRIDE 1040
#define SMB_A    0
#define SMB_BIAS 10752
#define SMB_B    12800           // + 160*1040 = 179200

// ---------------- roleA (lstm12, 32 rows) smem layout ----------------
#define APITCH12  656            // 32 rows x 656B = 20992
#define BPITCH12  2064
#define TILE12    66048          // 32*2064
#define SA_A      0
#define SA_BIAS   20992          // float4[256] = 4096
#define SA_B0     25088
#define SA_B1     (SA_B0 + TILE12)
#define SA_B2     (SA_B1 + TILE12)
#define SMEM_MERGED (SA_B2 + TILE12)   // 223232 < 227KB cap

// ---------------- weight prep ----------------
__global__ void prep_kernel(
    const float* __restrict__ Wih1, const float* __restrict__ Whh1,
    const float* __restrict__ bih1, const float* __restrict__ bhh1,
    const float* __restrict__ Wih2, const float* __restrict__ Whh2,
    const float* __restrict__ bih2, const float* __restrict__ bhh2,
    const float* __restrict__ bih3, const float* __restrict__ bhh3)
{
    int idx = blockIdx.x * blockDim.x + threadIdx.x;
    if (idx < 320 * 1024) {
        int k = idx >> 10, n = idx & 1023;
        int tau = n >> 8, j = n & 255;
        int g = tau * H1_ + j;
        float v1 = (k < IN1_) ? Wih1[g * IN1_ + k] : Whh1[g * H1_ + (k - IN1_)];
        float v2 = (k < IN1_) ? Wih2[g * IN1_ + k] : Whh2[g * H1_ + (k - IN1_)];
        g_W1h[idx] = __float2half_rn(v1);
        g_W2h[idx] = __float2half_rn(v2);
    }
    if (idx < H1_) {
        int j = idx;
        g_b1v4[j] = make_float4(bih1[j] + bhh1[j],
                                bih1[H1_ + j] + bhh1[H1_ + j],
                                bih1[2 * H1_ + j] + bhh1[2 * H1_ + j],
                                bih1[3 * H1_ + j] + bhh1[3 * H1_ + j]);
        g_b2v4[j] = make_float4(bih2[j] + bhh2[j],
                                bih2[H1_ + j] + bhh2[H1_ + j],
                                bih2[2 * H1_ + j] + bhh2[2 * H1_ + j],
                                bih2[3 * H1_ + j] + bhh2[3 * H1_ + j]);
    }
    if (idx < H3_ * 4) {
        int tau = idx & 3, j = idx >> 2;
        g_b3[j * 4 + tau] = bih3[tau * H3_ + j] + bhh3[tau * H3_ + j];
    }
}

// ---------------------------------------------------------------------------
// Merged LSTM kernel: 432 blocks x 512 threads (16 warps, 4/SMSP).
//   blocks 0..47   : roleA = LSTM1/2, 32 rows; B streamed (3 bufs, 1 sync/tile)
//   blocks 48..431 : roleB = LSTM3, 32 rows; B smem-resident
// Warp split: (rt = wid>>3) x (jq = wid&7). roleA jq covers 32 j; roleB 16 j.
// ---------------------------------------------------------------------------
__global__ __launch_bounds__(512, 1) void lstm_merged(
    const float* __restrict__ games_home, const float* __restrict__ games_away,
    const float* __restrict__ games_vs,
    const float* __restrict__ ph, const float* __restrict__ pa,
    const float* __restrict__ Wih3, const float* __restrict__ Whh3)
{
    extern __shared__ __align__(16) char sm[];
    const u32 sbase = smem_u32(sm);
    const int tid = threadIdx.x, wid = tid >> 5, lane = tid & 31;
    const int rt = wid >> 3, jq = wid & 7;
    const int g = lane >> 2, tig = lane & 3;

    if (blockIdx.x < 48) {
        // =================== roleA: LSTM1/2, 32 rows ===================
        const int b = blockIdx.x;
        const bool is1 = (b < 32);
        const int row0 = (is1 ? b : (b - 32)) * 32;
        const char* gB = (const char*)(is1 ? g_W1h : g_W2h);

        if (tid < 256) ((float4*)(sm + SA_BIAS))[tid] = (is1 ? g_b1v4 : g_b2v4)[tid];
        for (int i = tid; i < 32 * APITCH12 / 8; i += 512) ((u64*)(sm + SA_A))[i] = 0ull;

        // x loader: 32 rows x 16 threads/row, 1 float4 each
        const int xr = tid >> 4, xq = tid & 15;
        const int gxr = row0 + xr;
        const float* xrowp = is1 ? ((gxr < 512) ? games_home + (size_t)gxr * (T1_ * IN1_)
                                                : games_away + (size_t)(gxr - 512) * (T1_ * IN1_))
                                 : games_vs + (size_t)gxr * (T1_ * IN1_);
        const float4* xsrc = (const float4*)xrowp + xq;
        char* xdst = sm + SA_A + xr * APITCH12 + xq * 8;

        const u32 a_addr = sbase + SA_A + (u32)((rt * 16 + (lane & 15)) * APITCH12 + (lane >> 4) * 16);
        const u32 b_lane = (u32)((lane & 15) * BPITCH12 + (lane >> 4) * 16);

        char* hs_lo = sm + SA_A + (rt * 16 + g) * APITCH12 + (IN1_ + jq * 32 + 2 * tig) * 2;
        char* hs_hi = hs_lo + 8 * APITCH12;

        float acc[4][4][4];
        float cst[16], hreg[16];
#pragma unroll
        for (int i = 0; i < 16; i++) { cst[i] = 0.0f; hreg[i] = 0.0f; }

        const u32 bufs[3] = { sbase + SA_B0, sbase + SA_B1, sbase + SA_B2 };
        // prefetch tiles 0,1 into bufs 0,1 (each tile = 4096 16B chunks)
#pragma unroll
        for (int pt = 0; pt < 2; pt++) {
#pragma unroll
            for (int q = 0; q < 8; q++) {
                int c = tid + 512 * q;
                int row = c >> 7, col = (c & 127) * 16;
                cp16(bufs[pt] + (u32)(row * BPITCH12 + col), gB + (pt * 32 + row) * 2048 + col);
            }
            cp_commit();
        }
        __syncthreads();

        int cur = 0;                       // buffer of current tile
        for (int t = 0; t < T1_; t++) {
            // phase 1: x_t + h_{t-1} -> A
            float4 xv = __ldg(xsrc + t * 16);
            *(__half2*)(xdst)     = __floats2half2_rn(xv.x, xv.y);
            *(__half2*)(xdst + 4) = __floats2half2_rn(xv.z, xv.w);
#pragma unroll
            for (int sub = 0; sub < 4; sub++) {
                *(__half2*)(hs_lo + sub * 16) = __floats2half2_rn(hreg[sub * 4 + 0], hreg[sub * 4 + 1]);
                *(__half2*)(hs_hi + sub * 16) = __floats2half2_rn(hreg[sub * 4 + 2], hreg[sub * 4 + 3]);
            }
            __syncthreads();

#pragma unroll
            for (int i = 0; i < 64; i++) ((float*)acc)[i] = 0.0f;

            // phase 2: K loop, 10 streamed tiles, ONE sync per tile
            for (int kt = 0; kt < 10; kt++) {
                cp_wait<1>();              // current tile landed
                __syncthreads();           // + all warps done with previous tile
                // refill buffer (cur+2)%3 (held tile kt-1; drained) with tile kt+2
                {
                    const u32 rbuf = bufs[(cur + 2) % 3];
                    const int nt = (kt + 2) % 10;
#pragma unroll
                    for (int q = 0; q < 8; q++) {
                        int c = tid + 512 * q;
                        int row = c >> 7, col = (c & 127) * 16;
                        cp16(rbuf + (u32)(row * BPITCH12 + col), gB + (nt * 32 + row) * 2048 + col);
                    }
                    cp_commit();
                }
                const u32 buf = bufs[cur];
#pragma unroll
                for (int ks = 0; ks < 2; ks++) {
                    u32 a0, a1, a2, a3;
                    ldsm_x4(a0, a1, a2, a3, a_addr + (u32)((kt * 2 + ks) * 32));
                    const u32 bk = buf + b_lane + (u32)(ks * 16 * BPITCH12);
#pragma unroll
                    for (int gi = 0; gi < 4; gi++) {
#pragma unroll
                        for (int sp = 0; sp < 2; sp++) {
                            u32 b0, b1, b2, b3;
                            ldsm_x4t(b0, b1, b2, b3,
                                     bk + (u32)((gi * 256 + jq * 32 + sp * 16) * 2));
                            mma16816(acc[gi][2 * sp],     a0, a1, a2, a3, b0, b1);
                            mma16816(acc[gi][2 * sp + 1], a0, a1, a2, a3, b2, b3);
                        }
                    }
                }
                cur = (cur + 1) % 3;
            }

            // phase 3: cell update
            const float4* bias4 = (const float4*)(sm + SA_BIAS);
#pragma unroll
            for (int sub = 0; sub < 4; sub++) {
                const int jb = jq * 32 + sub * 8 + 2 * tig;
#pragma unroll
                for (int cc = 0; cc < 4; cc++) {
                    int j = jb + (cc & 1);
                    float4 b4 = bias4[j];
                    float iv = sga(acc[0][sub][cc] + b4.x);
                    float fv = sga(acc[1][sub][cc] + b4.y);
                    float gv = tapx(acc[2][sub][cc] + b4.z);
                    float ov = sga(acc[3][sub][cc] + b4.w);
                    int ci = sub * 4 + cc;
                    float cn = fv * cst[ci] + iv * gv;
                    cst[ci] = cn;
                    hreg[ci] = ov * tapx(cn);
                }
            }
        }

        // final h -> g_feat
#pragma unroll
        for (int half = 0; half < 2; half++) {
            int gr = row0 + rt * 16 + g + half * 8;
            float* fp;
            if (is1) fp = g_feat + (size_t)(gr & 511) * FEATC + ((gr < 512) ? 0 : 256);
            else     fp = g_feat + (size_t)gr * FEATC + 512;
#pragma unroll
            for (int sub = 0; sub < 4; sub++) {
                int j = jq * 32 + sub * 8 + 2 * tig;
                fp[j]     = hreg[sub * 4 + half * 2 + 0];
                fp[j + 1] = hreg[sub * 4 + half * 2 + 1];
            }
        }
    } else {
        // =================== roleB: LSTM3, 32 rows ===================
        const int row0 = (blockIdx.x - 48) * 32;

        for (int idx = tid; idx < 512 * 160; idx += 512) {
            int n = idx / 160, k = idx - n * 160;
            float v = (k < IN3_) ? Wih3[n * IN3_ + k] : Whh3[n * H3_ + (k - IN3_)];
            *(__half*)(sm + SMB_B + k * BSTRIDE + n * 2) = __float2half_rn(v);
        }
        if (tid < 512) ((float*)(sm + SMB_BIAS))[tid & 511] = g_b3[tid & 511];

        // x loader: 32 rows x 8 threads/row (tid<256), 1 float4 each
        const int xr = tid >> 3, xq = tid & 7;
        const int gxr = row0 + (xr & 31);
        const bool hmx = (gxr < 6144);
        const int gx2 = hmx ? gxr : gxr - 6144;
        const float4* xsrc = (const float4*)((hmx ? ph : pa) + (size_t)gx2 * (T3_ * IN3_)) + xq;
        char* xdst = sm + SMB_A + (xr & 31) * ASTRIDE + xq * 8;
        const bool xact = (tid < 256);

        const u32 a_addr = sbase + SMB_A + (u32)((rt * 16 + (lane & 15)) * ASTRIDE + (lane >> 4) * 16);
        const u32 b_addr = sbase + SMB_B + (u32)((lane & 15) * BSTRIDE + (lane >> 4) * 16);

        char* hs_lo = sm + SMB_A + (rt * 16 + g) * ASTRIDE + (IN3_ + jq * 16 + 2 * tig) * 2;
        char* hs_hi = hs_lo + 8 * ASTRIDE;

        float acc[4][2][4];
        float cst[8], hreg[8];
#pragma unroll
        for (int i = 0; i < 8; i++) { cst[i] = 0.0f; hreg[i] = 0.0f; }

        __syncthreads();

        for (int t = 0; t < T3_; t++) {
            if (xact) {
                float4 xv = __ldg(xsrc + t * 8);
                *(__half2*)(xdst)     = __floats2half2_rn(xv.x, xv.y);
                *(__half2*)(xdst + 4) = __floats2half2_rn(xv.z, xv.w);
            }
#pragma unroll
            for (int sub = 0; sub < 2; sub++) {
                *(__half2*)(hs_lo + sub * 16) = __floats2half2_rn(hreg[sub * 4 + 0], hreg[sub * 4 + 1]);
                *(__half2*)(hs_hi + sub * 16) = __floats2half2_rn(hreg[sub * 4 + 2], hreg[sub * 4 + 3]);
            }
            __syncthreads();

#pragma unroll
            for (int i = 0; i < 32; i++) ((float*)acc)[i] = 0.0f;

#pragma unroll
            for (int kt = 0; kt < 10; kt++) {
                u32 a0, a1, a2, a3;
                ldsm_x4(a0, a1, a2, a3, a_addr + kt * 32);
#pragma unroll
                for (int gi = 0; gi < 4; gi++) {
                    u32 b0, b1, b2, b3;
                    ldsm_x4t(b0, b1, b2, b3,
                             b_addr + (u32)(kt * 16 * BSTRIDE + (gi * 128 + jq * 16) * 2));
                    mma16816(acc[gi][0], a0, a1, a2, a3, b0, b1);
                    mma16816(acc[gi][1], a0, a1, a2, a3, b2, b3);
                }
            }
            __syncthreads();

            const float4* bias4 = (const float4*)(sm + SMB_BIAS);
#pragma unroll
            for (int sub = 0; sub < 2; sub++) {
                const int jb = jq * 16 + sub * 8 + 2 * tig;
#pragma unroll
                for (int cc = 0; cc < 4; cc++) {
                    int j = jb + (cc & 1);
                    float4 b4 = bias4[j];
                    float iv = sga(acc[0][sub][cc] + b4.x);
                    float fv = sga(acc[1][sub][cc] + b4.y);
                    float gv = tapx(acc[2][sub][cc] + b4.z);
                    float ov = sga(acc[3][sub][cc] + b4.w);
                    int ci = sub * 4 + cc;
                    float cn = fv * cst[ci] + iv * gv;
                    cst[ci] = cn;
                    hreg[ci] = ov * tapx(cn);
                }
            }
        }

#pragma unroll
        for (int half = 0; half < 2; half++) {
            int gr = row0 + rt * 16 + g + half * 8;
            bool hm = (gr < 6144);
            int g2 = hm ? gr : gr - 6144;
            int bb = g2 / 12, pp = g2 - 12 * bb;
            float* fp = g_feat + (size_t)bb * FEATC + (hm ? 768 : 2304) + pp * H3_;
#pragma unroll
            for (int sub = 0; sub < 2; sub++) {
                int j = jq * 16 + sub * 8 + 2 * tig;
                fp[j]     = hreg[sub * 4 + half * 2 + 0];
                fp[j + 1] = hreg[sub * 4 + half * 2 + 1];
            }
        }
    }
}

// ---------------- FC ----------------
__global__ void fc_kernel(const float* __restrict__ cg, const float* __restrict__ Wfc,
                          const float* __restrict__ bfc, float* __restrict__ out)
{
    const int b = blockIdx.x, tid = threadIdx.x;   // 128 threads
    const float* f = g_feat + b * FEATC;
    float a0 = 0.0f, a1 = 0.0f;
    for (int i = tid; i < FEATC; i += 128) {
        float v = f[i];
        a0 = fmaf(v, Wfc[i], a0);
        a1 = fmaf(v, Wfc[FCIN_ + i], a1);
    }
    if (tid < 32) {
        float v = cg[b * 32 + tid];
        a0 = fmaf(v, Wfc[FEATC + tid], a0);
        a1 = fmaf(v, Wfc[FCIN_ + FEATC + tid], a1);
    }
#pragma unroll
    for (int o = 16; o > 0; o >>= 1) {
        a0 += __shfl_down_sync(0xffffffffu, a0, o);
        a1 += __shfl_down_sync(0xffffffffu, a1, o);
    }
    __shared__ float r0[4], r1[4];
    int w = tid >> 5, l = tid & 31;
    if (l == 0) { r0[w] = a0; r1[w] = a1; }
    __syncthreads();
    if (tid == 0) {
        out[b * 2 + 0] = r0[0] + r0[1] + r0[2] + r0[3] + bfc[0];
        out[b * 2 + 1] = r1[0] + r1[1] + r1[2] + r1[3] + bfc[1];
    }
}

// ---------------- kernel_launch ----------------
extern "C" void kernel_launch(void* const* d_in, const int* in_sizes, int n_in,
                              void* d_out, int out_size)
{
    (void)in_sizes; (void)n_in; (void)out_size;
    const float* current_game = (const float*)d_in[0];
    const float* games_home   = (const float*)d_in[1];
    const float* games_away   = (const float*)d_in[2];
    const float* games_vs     = (const float*)d_in[3];
    const float* players_home = (const float*)d_in[4];
    const float* players_away = (const float*)d_in[5];
    const float* Wih1 = (const float*)d_in[6];
    const float* Whh1 = (const float*)d_in[7];
    const float* bih1 = (const float*)d_in[8];
    const float* bhh1 = (const float*)d_in[9];
    const float* Wih2 = (const float*)d_in[10];
    const float* Whh2 = (const float*)d_in[11];
    const float* bih2 = (const float*)d_in[12];
    const float* bhh2 = (const float*)d_in[13];
    const float* Wih3 = (const float*)d_in[14];
    const float* Whh3 = (const float*)d_in[15];
    const float* bih3 = (const float*)d_in[16];
    const float* bhh3 = (const float*)d_in[17];
    const float* Wfc  = (const float*)d_in[18];
    const float* bfc  = (const float*)d_in[19];

    cudaFuncSetAttribute(lstm_merged, cudaFuncAttributeMaxDynamicSharedMemorySize, SMEM_MERGED);

    prep_kernel<<<1280, 256>>>(Wih1, Whh1, bih1, bhh1,
                               Wih2, Whh2, bih2, bhh2, bih3, bhh3);
    lstm_merged<<<432, 512, SMEM_MERGED>>>(games_home, games_away, games_vs,
                                           players_home, players_away, Wih3, Whh3);
    fc_kernel<<<512, 128>>>(current_game, Wfc, bfc, (float*)d_out);
}

// round 11
// speedup vs baseline: 1.3945x; 1.3945x over previous
#include <cuda_runtime.h>
#include <cuda_fp16.h>
#include <cstdint>

#define B_    512
#define T1_   128
#define IN1_  64
#define H1_   256
#define IN3_  32
#define H3_   128
#define T3_   64
#define FCIN_ 3872
#define FEATC 3840

typedef unsigned long long u64;
typedef unsigned int u32;

// ---------------- device scratch ----------------
__device__ __align__(16) __half g_W1h[320 * 1024];   // [k][n], n=gate*256+j, pitch 2048B
__device__ __align__(16) __half g_W2h[320 * 1024];
__device__ __align__(16) float4 g_b1v4[H1_];         // (bi,bf,bg,bo) per j
__device__ __align__(16) float4 g_b2v4[H1_];
__device__ __align__(16) float  g_b3[H3_ * 4];       // [j][(bi,bf,bg,bo)]
__device__ float g_feat[B_ * FEATC];

// ---------------- scalar helpers ----------------
__device__ __forceinline__ float tapx(float x) {           // HW tanh (MUFU)
    float y; asm("tanh.approx.f32 %0, %1;" : "=f"(y) : "f"(x)); return y;
}
__device__ __forceinline__ float sga(float x) {            // sigmoid via tanh
    return fmaf(tapx(0.5f * x), 0.5f, 0.5f);
}
__device__ __forceinline__ u32 smem_u32(const void* p) {
    u32 a;
    asm("{ .reg .u64 t; cvta.to.shared.u64 t, %1; cvt.u32.u64 %0, t; }" : "=r"(a) : "l"(p));
    return a;
}

// ---------------- mma.sync / ldmatrix / cp.async ----------------
__device__ __forceinline__ void ldsm_x4(u32& r0, u32& r1, u32& r2, u32& r3, u32 addr) {
    asm volatile("ldmatrix.sync.aligned.m8n8.x4.shared.b16 {%0,%1,%2,%3}, [%4];"
                 : "=r"(r0), "=r"(r1), "=r"(r2), "=r"(r3) : "r"(addr));
}
// x4 trans: {r0,r1} = B-frag of n-tile at n_off, {r2,r3} = n-tile at n_off+8.
__device__ __forceinline__ void ldsm_x4t(u32& r0, u32& r1, u32& r2, u32& r3, u32 addr) {
    asm volatile("ldmatrix.sync.aligned.m8n8.x4.trans.shared.b16 {%0,%1,%2,%3}, [%4];"
                 : "=r"(r0), "=r"(r1), "=r"(r2), "=r"(r3) : "r"(addr));
}
__device__ __forceinline__ void mma16816(float* c, u32 a0, u32 a1, u32 a2, u32 a3,
                                         u32 b0, u32 b1) {
    asm volatile("mma.sync.aligned.m16n8k16.row.col.f32.f16.f16.f32 "
                 "{%0,%1,%2,%3}, {%4,%5,%6,%7}, {%8,%9}, {%0,%1,%2,%3};"
                 : "+f"(c[0]), "+f"(c[1]), "+f"(c[2]), "+f"(c[3])
                 : "r"(a0), "r"(a1), "r"(a2), "r"(a3), "r"(b0), "r"(b1));
}
__device__ __forceinline__ void cp16(u32 saddr, const void* gptr) {
    asm volatile("cp.async.cg.shared.global [%0], [%1], 16;" :: "r"(saddr), "l"(gptr));
}
__device__ __forceinline__ void cp_commit() {
    asm volatile("cp.async.commit_group;" ::: "memory");
}
template<int N> __device__ __forceinline__ void cp_wait() {
    asm volatile("cp.async.wait_group %0;" :: "n"(N) : "memory");
}

// ---------------- roleB (lstm3) smem layout (proven) ----------------
#define ASTRIDE 336
#define BSTRIDE 1040
#define SMB_A    0
#define SMB_BIAS 10752
#define SMB_B    12800           // + 160*1040 = 179200

// ---------------- roleA (lstm12, 16 rows) smem layout ----------------
#define APITCH12  656            // 16 rows x 656B = 10496
#define BPITCH12  2064
#define TILE12    66048          // 32*2064
#define SA_A      0
#define SA_BIAS   10496          // float4[256] = 4096
#define SA_B0     14592
#define SA_B1     (SA_B0 + TILE12)
// roleA total = 14592 + 2*66048 = 146688 < 179200

#define SMEM_MERGED 179200

// ---------------- weight prep ----------------
__global__ void prep_kernel(
    const float* __restrict__ Wih1, const float* __restrict__ Whh1,
    const float* __restrict__ bih1, const float* __restrict__ bhh1,
    const float* __restrict__ Wih2, const float* __restrict__ Whh2,
    const float* __restrict__ bih2, const float* __restrict__ bhh2,
    const float* __restrict__ bih3, const float* __restrict__ bhh3)
{
    int idx = blockIdx.x * blockDim.x + threadIdx.x;
    if (idx < 320 * 1024) {
        int k = idx >> 10, n = idx & 1023;
        int tau = n >> 8, j = n & 255;
        int g = tau * H1_ + j;
        float v1 = (k < IN1_) ? Wih1[g * IN1_ + k] : Whh1[g * H1_ + (k - IN1_)];
        float v2 = (k < IN1_) ? Wih2[g * IN1_ + k] : Whh2[g * H1_ + (k - IN1_)];
        g_W1h[idx] = __float2half_rn(v1);
        g_W2h[idx] = __float2half_rn(v2);
    }
    if (idx < H1_) {
        int j = idx;
        g_b1v4[j] = make_float4(bih1[j] + bhh1[j],
                                bih1[H1_ + j] + bhh1[H1_ + j],
                                bih1[2 * H1_ + j] + bhh1[2 * H1_ + j],
                                bih1[3 * H1_ + j] + bhh1[3 * H1_ + j]);
        g_b2v4[j] = make_float4(bih2[j] + bhh2[j],
                                bih2[H1_ + j] + bhh2[H1_ + j],
                                bih2[2 * H1_ + j] + bhh2[2 * H1_ + j],
                                bih2[3 * H1_ + j] + bhh2[3 * H1_ + j]);
    }
    if (idx < H3_ * 4) {
        int tau = idx & 3, j = idx >> 2;
        g_b3[j * 4 + tau] = bih3[tau * H3_ + j] + bhh3[tau * H3_ + j];
    }
}

// ---------------------------------------------------------------------------
// Merged LSTM kernel: 480 blocks x 256 threads (8 warps).
//   blocks 0..95   : roleA = LSTM1/2, 16 rows/block (b<64: LSTM1, else LSTM2),
//                    B streamed via cp.async (2 buffers, circular over 10 tiles)
//   blocks 96..479 : roleB = LSTM3, 32 rows/block, B smem-resident
// ---------------------------------------------------------------------------
__global__ __launch_bounds__(256, 1) void lstm_merged(
    const float* __restrict__ games_home, const float* __restrict__ games_away,
    const float* __restrict__ games_vs,
    const float* __restrict__ ph, const float* __restrict__ pa,
    const float* __restrict__ Wih3, const float* __restrict__ Whh3)
{
    extern __shared__ __align__(16) char sm[];
    const u32 sbase = smem_u32(sm);
    const int tid = threadIdx.x, wid = tid >> 5, lane = tid & 31;
    const int g = lane >> 2, tig = lane & 3;

    if (blockIdx.x < 96) {
        // =================== roleA: LSTM1/2, 16 rows ===================
        const int b = blockIdx.x;
        const bool is1 = (b < 64);
        const int row0 = (is1 ? b : (b - 64)) * 16;
        const char* gB = (const char*)(is1 ? g_W1h : g_W2h);

        ((float4*)(sm + SA_BIAS))[tid] = (is1 ? g_b1v4 : g_b2v4)[tid];
        for (int i = tid; i < 16 * APITCH12 / 8; i += 256) ((u64*)(sm + SA_A))[i] = 0ull;

        // x loader: 16 rows x 16 threads/row, 1 float4 each
        const int xr = tid >> 4, xq = tid & 15;
        const int gxr = row0 + xr;
        const float* xrowp = is1 ? ((gxr < 512) ? games_home + (size_t)gxr * (T1_ * IN1_)
                                                : games_away + (size_t)(gxr - 512) * (T1_ * IN1_))
                                 : games_vs + (size_t)gxr * (T1_ * IN1_);
        const float4* xsrc = (const float4*)xrowp + xq;
        char* xdst = sm + SA_A + xr * APITCH12 + xq * 8;

        const int jq = wid;   // warp covers 32 j for all 4 gates
        const u32 a_addr = sbase + SA_A + (u32)((lane & 15) * APITCH12 + (lane >> 4) * 16);
        const u32 b_lane = (u32)((lane & 15) * BPITCH12 + (lane >> 4) * 16);

        char* hs_lo = sm + SA_A + g * APITCH12 + (IN1_ + jq * 32 + 2 * tig) * 2;
        char* hs_hi = hs_lo + 8 * APITCH12;

        float acc[4][4][4];
        float cst[16], hreg[16];
#pragma unroll
        for (int i = 0; i < 16; i++) { cst[i] = 0.0f; hreg[i] = 0.0f; }

        const u32 bufs[2] = { sbase + SA_B0, sbase + SA_B1 };
        // prefetch tiles 0,1 (each tile = 4096 16B chunks over 256 threads)
#pragma unroll
        for (int pt = 0; pt < 2; pt++) {
#pragma unroll
            for (int q = 0; q < 16; q++) {
                int c = tid + 256 * q;
                int row = c >> 7, col = (c & 127) * 16;
                cp16(bufs[pt] + (u32)(row * BPITCH12 + col), gB + (pt * 32 + row) * 2048 + col);
            }
            cp_commit();
        }
        __syncthreads();

        for (int t = 0; t < T1_; t++) {
            // phase 1: x_t + h_{t-1} -> A
            float4 xv = __ldg(xsrc + t * 16);
            *(__half2*)(xdst)     = __floats2half2_rn(xv.x, xv.y);
            *(__half2*)(xdst + 4) = __floats2half2_rn(xv.z, xv.w);
#pragma unroll
            for (int sub = 0; sub < 4; sub++) {
                *(__half2*)(hs_lo + sub * 16) = __floats2half2_rn(hreg[sub * 4 + 0], hreg[sub * 4 + 1]);
                *(__half2*)(hs_hi + sub * 16) = __floats2half2_rn(hreg[sub * 4 + 2], hreg[sub * 4 + 3]);
            }
            __syncthreads();

#pragma unroll
            for (int i = 0; i < 64; i++) ((float*)acc)[i] = 0.0f;

            // phase 2: K loop over 10 streamed tiles (2 bufs, 2 syncs/tile)
            for (int kt = 0; kt < 10; kt++) {
                const u32 buf = bufs[kt & 1];
                cp_wait<1>();
                __syncthreads();
#pragma unroll
                for (int ks = 0; ks < 2; ks++) {
                    u32 a0, a1, a2, a3;
                    ldsm_x4(a0, a1, a2, a3, a_addr + (u32)((kt * 2 + ks) * 32));
                    const u32 bk = buf + b_lane + (u32)(ks * 16 * BPITCH12);
#pragma unroll
                    for (int gi = 0; gi < 4; gi++) {
#pragma unroll
                        for (int sp = 0; sp < 2; sp++) {
                            u32 b0, b1, b2, b3;
                            ldsm_x4t(b0, b1, b2, b3,
                                     bk + (u32)((gi * 256 + jq * 32 + sp * 16) * 2));
                            mma16816(acc[gi][2 * sp],     a0, a1, a2, a3, b0, b1);
                            mma16816(acc[gi][2 * sp + 1], a0, a1, a2, a3, b2, b3);
                        }
                    }
                }
                __syncthreads();
                int nt = (kt + 2) % 10;
#pragma unroll
                for (int q = 0; q < 16; q++) {
                    int c = tid + 256 * q;
                    int row = c >> 7, col = (c & 127) * 16;
                    cp16(buf + (u32)(row * BPITCH12 + col), gB + (nt * 32 + row) * 2048 + col);
                }
                cp_commit();
            }

            // phase 3: cell update
            const float4* bias4 = (const float4*)(sm + SA_BIAS);
#pragma unroll
            for (int sub = 0; sub < 4; sub++) {
                const int jb = jq * 32 + sub * 8 + 2 * tig;
#pragma unroll
                for (int cc = 0; cc < 4; cc++) {
                    int j = jb + (cc & 1);
                    float4 b4 = bias4[j];
                    float iv = sga(acc[0][sub][cc] + b4.x);
                    float fv = sga(acc[1][sub][cc] + b4.y);
                    float gv = tapx(acc[2][sub][cc] + b4.z);
                    float ov = sga(acc[3][sub][cc] + b4.w);
                    int ci = sub * 4 + cc;
                    float cn = fv * cst[ci] + iv * gv;
                    cst[ci] = cn;
                    hreg[ci] = ov * tapx(cn);
                }
            }
        }

        // final h -> g_feat
#pragma unroll
        for (int half = 0; half < 2; half++) {
            int gr = row0 + g + half * 8;
            float* fp;
            if (is1) fp = g_feat + (size_t)(gr & 511) * FEATC + ((gr < 512) ? 0 : 256);
            else     fp = g_feat + (size_t)gr * FEATC + 512;
#pragma unroll
            for (int sub = 0; sub < 4; sub++) {
                int j = jq * 32 + sub * 8 + 2 * tig;
                fp[j]     = hreg[sub * 4 + half * 2 + 0];
                fp[j + 1] = hreg[sub * 4 + half * 2 + 1];
            }
        }
    } else {
        // =================== roleB: LSTM3, 32 rows (proven) ===================
        const int row0 = (blockIdx.x - 96) * 32;
        const int rt = wid >> 2, jq = wid & 3;

        for (int idx = tid; idx < 512 * 160; idx += 256) {
            int n = idx / 160, k = idx - n * 160;
            float v = (k < IN3_) ? Wih3[n * IN3_ + k] : Whh3[n * H3_ + (k - IN3_)];
            *(__half*)(sm + SMB_B + k * BSTRIDE + n * 2) = __float2half_rn(v);
        }
        for (int i = tid; i < 512; i += 256)
            ((float*)(sm + SMB_BIAS))[i] = g_b3[i];

        const int xr = tid >> 3, xq = tid & 7;
        const int gxr = row0 + xr;
        const bool hmx = (gxr < 6144);
        const int gx2 = hmx ? gxr : gxr - 6144;
        const float4* xsrc = (const float4*)((hmx ? ph : pa) + (size_t)gx2 * (T3_ * IN3_)) + xq;
        char* xdst = sm + SMB_A + xr * ASTRIDE + xq * 8;

        const u32 a_addr = sbase + SMB_A + (u32)((rt * 16 + (lane & 15)) * ASTRIDE + (lane >> 4) * 16);
        const u32 b_addr = sbase + SMB_B + (u32)((lane & 15) * BSTRIDE + (lane >> 4) * 16);

        char* hs_lo = sm + SMB_A + (rt * 16 + g) * ASTRIDE + (IN3_ + jq * 32 + 2 * tig) * 2;
        char* hs_hi = hs_lo + 8 * ASTRIDE;

        float acc[4][4][4];
        float cst[16], hreg[16];
#pragma unroll
        for (int i = 0; i < 16; i++) { cst[i] = 0.0f; hreg[i] = 0.0f; }

        __syncthreads();

        for (int t = 0; t < T3_; t++) {
            float4 xv = __ldg(xsrc + t * 8);
            *(__half2*)(xdst)     = __floats2half2_rn(xv.x, xv.y);
            *(__half2*)(xdst + 4) = __floats2half2_rn(xv.z, xv.w);
#pragma unroll
            for (int sub = 0; sub < 4; sub++) {
                *(__half2*)(hs_lo + sub * 16) = __floats2half2_rn(hreg[sub * 4 + 0], hreg[sub * 4 + 1]);
                *(__half2*)(hs_hi + sub * 16) = __floats2half2_rn(hreg[sub * 4 + 2], hreg[sub * 4 + 3]);
            }
            __syncthreads();

#pragma unroll
            for (int i = 0; i < 64; i++) ((float*)acc)[i] = 0.0f;

#pragma unroll
            for (int kt = 0; kt < 10; kt++) {
                u32 a0, a1, a2, a3;
                ldsm_x4(a0, a1, a2, a3, a_addr + kt * 32);
#pragma unroll
                for (int gi = 0; gi < 4; gi++) {
#pragma unroll
                    for (int sp = 0; sp < 2; sp++) {
                        u32 b0, b1, b2, b3;
                        ldsm_x4t(b0, b1, b2, b3,
                                 b_addr + (u32)(kt * 16 * BSTRIDE + (gi * 128 + jq * 32 + sp * 16) * 2));
                        mma16816(acc[gi][2 * sp],     a0, a1, a2, a3, b0, b1);
                        mma16816(acc[gi][2 * sp + 1], a0, a1, a2, a3, b2, b3);
                    }
                }
            }
            __syncthreads();

            const float4* bias4 = (const float4*)(sm + SMB_BIAS);
#pragma unroll
            for (int sub = 0; sub < 4; sub++) {
                const int jb = jq * 32 + sub * 8 + 2 * tig;
#pragma unroll
                for (int cc = 0; cc < 4; cc++) {
                    int j = jb + (cc & 1);
                    float4 b4 = bias4[j];
                    float iv = sga(acc[0][sub][cc] + b4.x);
                    float fv = sga(acc[1][sub][cc] + b4.y);
                    float gv = tapx(acc[2][sub][cc] + b4.z);
                    float ov = sga(acc[3][sub][cc] + b4.w);
                    int ci = sub * 4 + cc;
                    float cn = fv * cst[ci] + iv * gv;
                    cst[ci] = cn;
                    hreg[ci] = ov * tapx(cn);
                }
            }
        }

#pragma unroll
        for (int half = 0; half < 2; half++) {
            int gr = row0 + rt * 16 + g + half * 8;
            bool hm = (gr < 6144);
            int g2 = hm ? gr : gr - 6144;
            int bb = g2 / 12, pp = g2 - 12 * bb;
            float* fp = g_feat + (size_t)bb * FEATC + (hm ? 768 : 2304) + pp * H3_;
#pragma unroll
            for (int sub = 0; sub < 4; sub++) {
                int j = jq * 32 + sub * 8 + 2 * tig;
                fp[j]     = hreg[sub * 4 + half * 2 + 0];
                fp[j + 1] = hreg[sub * 4 + half * 2 + 1];
            }
        }
    }
}

// ---------------- FC ----------------
__global__ void fc_kernel(const float* __restrict__ cg, const float* __restrict__ Wfc,
                          const float* __restrict__ bfc, float* __restrict__ out)
{
    const int b = blockIdx.x, tid = threadIdx.x;   // 128 threads
    const float* f = g_feat + b * FEATC;
    float a0 = 0.0f, a1 = 0.0f;
    for (int i = tid; i < FEATC; i += 128) {
        float v = f[i];
        a0 = fmaf(v, Wfc[i], a0);
        a1 = fmaf(v, Wfc[FCIN_ + i], a1);
    }
    if (tid < 32) {
        float v = cg[b * 32 + tid];
        a0 = fmaf(v, Wfc[FEATC + tid], a0);
        a1 = fmaf(v, Wfc[FCIN_ + FEATC + tid], a1);
    }
#pragma unroll
    for (int o = 16; o > 0; o >>= 1) {
        a0 += __shfl_down_sync(0xffffffffu, a0, o);
        a1 += __shfl_down_sync(0xffffffffu, a1, o);
    }
    __shared__ float r0[4], r1[4];
    int w = tid >> 5, l = tid & 31;
    if (l == 0) { r0[w] = a0; r1[w] = a1; }
    __syncthreads();
    if (tid == 0) {
        out[b * 2 + 0] = r0[0] + r0[1] + r0[2] + r0[3] + bfc[0];
        out[b * 2 + 1] = r1[0] + r1[1] + r1[2] + r1[3] + bfc[1];
    }
}

// ---------------- kernel_launch ----------------
extern "C" void kernel_launch(void* const* d_in, const int* in_sizes, int n_in,
                              void* d_out, int out_size)
{
    (void)in_sizes; (void)n_in; (void)out_size;
    const float* current_game = (const float*)d_in[0];
    const float* games_home   = (const float*)d_in[1];
    const float* games_away   = (const float*)d_in[2];
    const float* games_vs     = (const float*)d_in[3];
    const float* players_home = (const float*)d_in[4];
    const float* players_away = (const float*)d_in[5];
    const float* Wih1 = (const float*)d_in[6];
    const float* Whh1 = (const float*)d_in[7];
    const float* bih1 = (const float*)d_in[8];
    const float* bhh1 = (const float*)d_in[9];
    const float* Wih2 = (const float*)d_in[10];
    const float* Whh2 = (const float*)d_in[11];
    const float* bih2 = (const float*)d_in[12];
    const float* bhh2 = (const float*)d_in[13];
    const float* Wih3 = (const float*)d_in[14];
    const float* Whh3 = (const float*)d_in[15];
    const float* bih3 = (const float*)d_in[16];
    const float* bhh3 = (const float*)d_in[17];
    const float* Wfc  = (const float*)d_in[18];
    const float* bfc  = (const float*)d_in[19];

    cudaFuncSetAttribute(lstm_merged, cudaFuncAttributeMaxDynamicSharedMemorySize, SMEM_MERGED);

    prep_kernel<<<1280, 256>>>(Wih1, Whh1, bih1, bhh1,
                               Wih2, Whh2, bih2, bhh2, bih3, bhh3);
    lstm_merged<<<480, 256, SMEM_MERGED>>>(games_home, games_away, games_vs,
                                           players_home, players_away, Wih3, Whh3);
    fc_kernel<<<512, 128>>>(current_game, Wfc, bfc, (float*)d_out);
}

// round 12
// speedup vs baseline: 1.5267x; 1.0947x over previous
#include <cuda_runtime.h>
#include <cuda_fp16.h>
#include <cstdint>

#define B_    512
#define T1_   128
#define IN1_  64
#define H1_   256
#define IN3_  32
#define H3_   128
#define T3_   64
#define FCIN_ 3872
#define FEATC 3840

typedef unsigned long long u64;
typedef unsigned int u32;

// ---------------- device scratch ----------------
__device__ __align__(16) __half g_W1h[320 * 1024];   // [k][n], n=gate*256+j, pitch 2048B
__device__ __align__(16) __half g_W2h[320 * 1024];
__device__ __align__(16) float4 g_b1v4[H1_];         // (bi,bf,bg,bo) per j
__device__ __align__(16) float4 g_b2v4[H1_];
__device__ __align__(16) float  g_b3[H3_ * 4];       // [j][(bi,bf,bg,bo)]
__device__ float g_feat[B_ * FEATC];

// ---------------- scalar helpers ----------------
__device__ __forceinline__ float tapx(float x) {           // HW tanh (MUFU)
    float y; asm("tanh.approx.f32 %0, %1;" : "=f"(y) : "f"(x)); return y;
}
__device__ __forceinline__ float sga(float x) {            // sigmoid via tanh
    return fmaf(tapx(0.5f * x), 0.5f, 0.5f);
}
__device__ __forceinline__ u32 smem_u32(const void* p) {
    u32 a;
    asm("{ .reg .u64 t; cvta.to.shared.u64 t, %1; cvt.u32.u64 %0, t; }" : "=r"(a) : "l"(p));
    return a;
}

// ---------------- mma.sync / ldmatrix / cp.async ----------------
__device__ __forceinline__ void ldsm_x4(u32& r0, u32& r1, u32& r2, u32& r3, u32 addr) {
    asm volatile("ldmatrix.sync.aligned.m8n8.x4.shared.b16 {%0,%1,%2,%3}, [%4];"
                 : "=r"(r0), "=r"(r1), "=r"(r2), "=r"(r3) : "r"(addr));
}
// x4 trans: {r0,r1} = B-frag of n-tile at n_off, {r2,r3} = n-tile at n_off+8.
__device__ __forceinline__ void ldsm_x4t(u32& r0, u32& r1, u32& r2, u32& r3, u32 addr) {
    asm volatile("ldmatrix.sync.aligned.m8n8.x4.trans.shared.b16 {%0,%1,%2,%3}, [%4];"
                 : "=r"(r0), "=r"(r1), "=r"(r2), "=r"(r3) : "r"(addr));
}
__device__ __forceinline__ void mma16816(float* c, u32 a0, u32 a1, u32 a2, u32 a3,
                                         u32 b0, u32 b1) {
    asm volatile("mma.sync.aligned.m16n8k16.row.col.f32.f16.f16.f32 "
                 "{%0,%1,%2,%3}, {%4,%5,%6,%7}, {%8,%9}, {%0,%1,%2,%3};"
                 : "+f"(c[0]), "+f"(c[1]), "+f"(c[2]), "+f"(c[3])
                 : "r"(a0), "r"(a1), "r"(a2), "r"(a3), "r"(b0), "r"(b1));
}
__device__ __forceinline__ void cp16(u32 saddr, const void* gptr) {
    asm volatile("cp.async.cg.shared.global [%0], [%1], 16;" :: "r"(saddr), "l"(gptr));
}
__device__ __forceinline__ void cp_commit() {
    asm volatile("cp.async.commit_group;" ::: "memory");
}
template<int N> __device__ __forceinline__ void cp_wait() {
    asm volatile("cp.async.wait_group %0;" :: "n"(N) : "memory");
}

// ---------------- roleB (lstm3) smem layout: double-buffered A ----------------
#define ASTRIDE 336
#define BSTRIDE 1040
#define ABUFB   10752            // 32 rows x 336
#define SMB_A    0               // A0 at 0, A1 at 10752
#define SMB_BIAS 21504           // 2048 (float4[128])
#define SMB_B    23552           // + 160*1040 = 189952

// ---------------- roleA (lstm12, 16 rows) smem layout: 2xA + 3xB ----------------
#define APITCH12  656            // 16 rows x 656B = 10496
#define ABUFA     10496
#define BPITCH12  2064
#define TILE12    66048          // 32*2064
#define SA_A      0              // A0 at 0, A1 at 10496
#define SA_BIAS   20992          // float4[256] = 4096
#define SA_B0     25088
#define SA_B1     (SA_B0 + TILE12)
#define SA_B2     (SA_B1 + TILE12)
#define SMEM_MERGED (SA_B2 + TILE12)   // 223232 <= 227KB cap

// ---------------- weight prep ----------------
__global__ void prep_kernel(
    const float* __restrict__ Wih1, const float* __restrict__ Whh1,
    const float* __restrict__ bih1, const float* __restrict__ bhh1,
    const float* __restrict__ Wih2, const float* __restrict__ Whh2,
    const float* __restrict__ bih2, const float* __restrict__ bhh2,
    const float* __restrict__ bih3, const float* __restrict__ bhh3)
{
    int idx = blockIdx.x * blockDim.x + threadIdx.x;
    if (idx < 320 * 1024) {
        int k = idx >> 10, n = idx & 1023;
        int tau = n >> 8, j = n & 255;
        int g = tau * H1_ + j;
        float v1 = (k < IN1_) ? Wih1[g * IN1_ + k] : Whh1[g * H1_ + (k - IN1_)];
        float v2 = (k < IN1_) ? Wih2[g * IN1_ + k] : Whh2[g * H1_ + (k - IN1_)];
        g_W1h[idx] = __float2half_rn(v1);
        g_W2h[idx] = __float2half_rn(v2);
    }
    if (idx < H1_) {
        int j = idx;
        g_b1v4[j] = make_float4(bih1[j] + bhh1[j],
                                bih1[H1_ + j] + bhh1[H1_ + j],
                                bih1[2 * H1_ + j] + bhh1[2 * H1_ + j],
                                bih1[3 * H1_ + j] + bhh1[3 * H1_ + j]);
        g_b2v4[j] = make_float4(bih2[j] + bhh2[j],
                                bih2[H1_ + j] + bhh2[H1_ + j],
                                bih2[2 * H1_ + j] + bhh2[2 * H1_ + j],
                                bih2[3 * H1_ + j] + bhh2[3 * H1_ + j]);
    }
    if (idx < H3_ * 4) {
        int tau = idx & 3, j = idx >> 2;
        g_b3[j * 4 + tau] = bih3[tau * H3_ + j] + bhh3[tau * H3_ + j];
    }
}

// ---------------------------------------------------------------------------
// Merged LSTM kernel: 480 blocks x 256 threads (8 warps).
//   blocks 0..95   : roleA = LSTM1/2, 16 rows/block; B streamed via cp.async
//                    (3 buffers, ONE sync per tile); A double-buffered (t&1)
//   blocks 96..479 : roleB = LSTM3, 32 rows/block; B smem-resident;
//                    A double-buffered -> ONE sync per step
// Phase-1 fully rewrites x+h of A[t&1] every step, so reads of A[(t-1)&1]
// by slow warps never collide with next-step stores.
// ---------------------------------------------------------------------------
__global__ __launch_bounds__(256, 1) void lstm_merged(
    const float* __restrict__ games_home, const float* __restrict__ games_away,
    const float* __restrict__ games_vs,
    const float* __restrict__ ph, const float* __restrict__ pa,
    const float* __restrict__ Wih3, const float* __restrict__ Whh3)
{
    extern __shared__ __align__(16) char sm[];
    const u32 sbase = smem_u32(sm);
    const int tid = threadIdx.x, wid = tid >> 5, lane = tid & 31;
    const int g = lane >> 2, tig = lane & 3;

    if (blockIdx.x < 96) {
        // =================== roleA: LSTM1/2, 16 rows ===================
        const int b = blockIdx.x;
        const bool is1 = (b < 64);
        const int row0 = (is1 ? b : (b - 64)) * 16;
        const char* gB = (const char*)(is1 ? g_W1h : g_W2h);

        ((float4*)(sm + SA_BIAS))[tid] = (is1 ? g_b1v4 : g_b2v4)[tid];
        for (int i = tid; i < 2 * ABUFA / 8; i += 256) ((u64*)(sm + SA_A))[i] = 0ull;

        // x loader: 16 rows x 16 threads/row, 1 float4 each
        const int xr = tid >> 4, xq = tid & 15;
        const int gxr = row0 + xr;
        const float* xrowp = is1 ? ((gxr < 512) ? games_home + (size_t)gxr * (T1_ * IN1_)
                                                : games_away + (size_t)(gxr - 512) * (T1_ * IN1_))
                                 : games_vs + (size_t)gxr * (T1_ * IN1_);
        const float4* xsrc = (const float4*)xrowp + xq;
        char* xdst0 = sm + SA_A + xr * APITCH12 + xq * 8;

        const int jq = wid;   // warp covers 32 j for all 4 gates
        const u32 a_addr0 = sbase + SA_A + (u32)((lane & 15) * APITCH12 + (lane >> 4) * 16);
        const u32 b_lane = (u32)((lane & 15) * BPITCH12 + (lane >> 4) * 16);

        char* hs_lo0 = sm + SA_A + g * APITCH12 + (IN1_ + jq * 32 + 2 * tig) * 2;

        float acc[4][4][4];
        float cst[16], hreg[16];
#pragma unroll
        for (int i = 0; i < 16; i++) { cst[i] = 0.0f; hreg[i] = 0.0f; }

        const u32 bufs[3] = { sbase + SA_B0, sbase + SA_B1, sbase + SA_B2 };
        // prefetch tiles 0,1 into bufs 0,1
#pragma unroll
        for (int pt = 0; pt < 2; pt++) {
#pragma unroll
            for (int q = 0; q < 16; q++) {
                int c = tid + 256 * q;
                int row = c >> 7, col = (c & 127) * 16;
                cp16(bufs[pt] + (u32)(row * BPITCH12 + col), gB + (pt * 32 + row) * 2048 + col);
            }
            cp_commit();
        }
        __syncthreads();

        int cur = 0;   // buffer holding current tile
        int nt = 2;    // next tile index to fetch
        for (int t = 0; t < T1_; t++) {
            const int par = (t & 1) * ABUFA;
            // phase 1: x_t + h_{t-1} -> A[par]  (no sync; tile-0 sync orders it)
            float4 xv = __ldg(xsrc + t * 16);
            char* xd = xdst0 + par;
            *(__half2*)(xd)     = __floats2half2_rn(xv.x, xv.y);
            *(__half2*)(xd + 4) = __floats2half2_rn(xv.z, xv.w);
            char* hlo = hs_lo0 + par;
            char* hhi = hlo + 8 * APITCH12;
#pragma unroll
            for (int sub = 0; sub < 4; sub++) {
                *(__half2*)(hlo + sub * 16) = __floats2half2_rn(hreg[sub * 4 + 0], hreg[sub * 4 + 1]);
                *(__half2*)(hhi + sub * 16) = __floats2half2_rn(hreg[sub * 4 + 2], hreg[sub * 4 + 3]);
            }

#pragma unroll
            for (int i = 0; i < 64; i++) ((float*)acc)[i] = 0.0f;

            const u32 a_par = a_addr0 + (u32)par;
            // phase 2: 10 streamed tiles, ONE sync per tile
            for (int kt = 0; kt < 10; kt++) {
                cp_wait<1>();              // current tile landed (per-thread)
                __syncthreads();           // all landed + prev-tile reads done
                // refill the buffer read two tiles ago with tile nt
                {
                    const u32 rbuf = bufs[(cur + 2) % 3];
#pragma unroll
                    for (int q = 0; q < 16; q++) {
                        int c = tid + 256 * q;
                        int row = c >> 7, col = (c & 127) * 16;
                        cp16(rbuf + (u32)(row * BPITCH12 + col), gB + (nt * 32 + row) * 2048 + col);
                    }
                    cp_commit();
                }
                nt = (nt + 1) % 10;
                const u32 buf = bufs[cur];
#pragma unroll
                for (int ks = 0; ks < 2; ks++) {
                    u32 a0, a1, a2, a3;
                    ldsm_x4(a0, a1, a2, a3, a_par + (u32)((kt * 2 + ks) * 32));
                    const u32 bk = buf + b_lane + (u32)(ks * 16 * BPITCH12);
#pragma unroll
                    for (int gi = 0; gi < 4; gi++) {
#pragma unroll
                        for (int sp = 0; sp < 2; sp++) {
                            u32 b0, b1, b2, b3;
                            ldsm_x4t(b0, b1, b2, b3,
                                     bk + (u32)((gi * 256 + jq * 32 + sp * 16) * 2));
                            mma16816(acc[gi][2 * sp],     a0, a1, a2, a3, b0, b1);
                            mma16816(acc[gi][2 * sp + 1], a0, a1, a2, a3, b2, b3);
                        }
                    }
                }
                cur = (cur + 1) % 3;
            }

            // phase 3: cell update (register-local)
            const float4* bias4 = (const float4*)(sm + SA_BIAS);
#pragma unroll
            for (int sub = 0; sub < 4; sub++) {
                const int jb = jq * 32 + sub * 8 + 2 * tig;
#pragma unroll
                for (int cc = 0; cc < 4; cc++) {
                    int j = jb + (cc & 1);
                    float4 b4 = bias4[j];
                    float iv = sga(acc[0][sub][cc] + b4.x);
                    float fv = sga(acc[1][sub][cc] + b4.y);
                    float gv = tapx(acc[2][sub][cc] + b4.z);
                    float ov = sga(acc[3][sub][cc] + b4.w);
                    int ci = sub * 4 + cc;
                    float cn = fv * cst[ci] + iv * gv;
                    cst[ci] = cn;
                    hreg[ci] = ov * tapx(cn);
                }
            }
        }

        // final h -> g_feat
#pragma unroll
        for (int half = 0; half < 2; half++) {
            int gr = row0 + g + half * 8;
            float* fp;
            if (is1) fp = g_feat + (size_t)(gr & 511) * FEATC + ((gr < 512) ? 0 : 256);
            else     fp = g_feat + (size_t)gr * FEATC + 512;
#pragma unroll
            for (int sub = 0; sub < 4; sub++) {
                int j = jq * 32 + sub * 8 + 2 * tig;
                fp[j]     = hreg[sub * 4 + half * 2 + 0];
                fp[j + 1] = hreg[sub * 4 + half * 2 + 1];
            }
        }
    } else {
        // =================== roleB: LSTM3, 32 rows ===================
        const int row0 = (blockIdx.x - 96) * 32;
        const int rt = wid >> 2, jq = wid & 3;

        for (int idx = tid; idx < 512 * 160; idx += 256) {
            int n = idx / 160, k = idx - n * 160;
            float v = (k < IN3_) ? Wih3[n * IN3_ + k] : Whh3[n * H3_ + (k - IN3_)];
            *(__half*)(sm + SMB_B + k * BSTRIDE + n * 2) = __float2half_rn(v);
        }
        for (int i = tid; i < 512; i += 256)
            ((float*)(sm + SMB_BIAS))[i] = g_b3[i];
        for (int i = tid; i < 2 * ABUFB / 8; i += 256) ((u64*)(sm + SMB_A))[i] = 0ull;

        const int xr = tid >> 3, xq = tid & 7;
        const int gxr = row0 + xr;
        const bool hmx = (gxr < 6144);
        const int gx2 = hmx ? gxr : gxr - 6144;
        const float4* xsrc = (const float4*)((hmx ? ph : pa) + (size_t)gx2 * (T3_ * IN3_)) + xq;
        char* xdst0 = sm + SMB_A + xr * ASTRIDE + xq * 8;

        const u32 a_addr0 = sbase + SMB_A + (u32)((rt * 16 + (lane & 15)) * ASTRIDE + (lane >> 4) * 16);
        const u32 b_addr = sbase + SMB_B + (u32)((lane & 15) * BSTRIDE + (lane >> 4) * 16);

        char* hs_lo0 = sm + SMB_A + (rt * 16 + g) * ASTRIDE + (IN3_ + jq * 32 + 2 * tig) * 2;

        float acc[4][4][4];
        float cst[16], hreg[16];
#pragma unroll
        for (int i = 0; i < 16; i++) { cst[i] = 0.0f; hreg[i] = 0.0f; }

        __syncthreads();

        for (int t = 0; t < T3_; t++) {
            const int par = (t & 1) * ABUFB;
            // phase 1: x_t + h_{t-1} -> A[par]; ONE sync per step
            float4 xv = __ldg(xsrc + t * 8);
            char* xd = xdst0 + par;
            *(__half2*)(xd)     = __floats2half2_rn(xv.x, xv.y);
            *(__half2*)(xd + 4) = __floats2half2_rn(xv.z, xv.w);
            char* hlo = hs_lo0 + par;
            char* hhi = hlo + 8 * ASTRIDE;
#pragma unroll
            for (int sub = 0; sub < 4; sub++) {
                *(__half2*)(hlo + sub * 16) = __floats2half2_rn(hreg[sub * 4 + 0], hreg[sub * 4 + 1]);
                *(__half2*)(hhi + sub * 16) = __floats2half2_rn(hreg[sub * 4 + 2], hreg[sub * 4 + 3]);
            }
            __syncthreads();

#pragma unroll
            for (int i = 0; i < 64; i++) ((float*)acc)[i] = 0.0f;

            const u32 a_par = a_addr0 + (u32)par;
#pragma unroll
            for (int kt = 0; kt < 10; kt++) {
                u32 a0, a1, a2, a3;
                ldsm_x4(a0, a1, a2, a3, a_par + kt * 32);
#pragma unroll
                for (int gi = 0; gi < 4; gi++) {
#pragma unroll
                    for (int sp = 0; sp < 2; sp++) {
                        u32 b0, b1, b2, b3;
                        ldsm_x4t(b0, b1, b2, b3,
                                 b_addr + (u32)(kt * 16 * BSTRIDE + (gi * 128 + jq * 32 + sp * 16) * 2));
                        mma16816(acc[gi][2 * sp],     a0, a1, a2, a3, b0, b1);
                        mma16816(acc[gi][2 * sp + 1], a0, a1, a2, a3, b2, b3);
                    }
                }
            }
            // no post-MMA sync: next step writes the OTHER A buffer

            const float4* bias4 = (const float4*)(sm + SMB_BIAS);
#pragma unroll
            for (int sub = 0; sub < 4; sub++) {
                const int jb = jq * 32 + sub * 8 + 2 * tig;
#pragma unroll
                for (int cc = 0; cc < 4; cc++) {
                    int j = jb + (cc & 1);
                    float4 b4 = bias4[j];
                    float iv = sga(acc[0][sub][cc] + b4.x);
                    float fv = sga(acc[1][sub][cc] + b4.y);
                    float gv = tapx(acc[2][sub][cc] + b4.z);
                    float ov = sga(acc[3][sub][cc] + b4.w);
                    int ci = sub * 4 + cc;
                    float cn = fv * cst[ci] + iv * gv;
                    cst[ci] = cn;
                    hreg[ci] = ov * tapx(cn);
                }
            }
        }

#pragma unroll
        for (int half = 0; half < 2; half++) {
            int gr = row0 + rt * 16 + g + half * 8;
            bool hm = (gr < 6144);
            int g2 = hm ? gr : gr - 6144;
            int bb = g2 / 12, pp = g2 - 12 * bb;
            float* fp = g_feat + (size_t)bb * FEATC + (hm ? 768 : 2304) + pp * H3_;
#pragma unroll
            for (int sub = 0; sub < 4; sub++) {
                int j = jq * 32 + sub * 8 + 2 * tig;
                fp[j]     = hreg[sub * 4 + half * 2 + 0];
                fp[j + 1] = hreg[sub * 4 + half * 2 + 1];
            }
        }
    }
}

// ---------------- FC ----------------
__global__ void fc_kernel(const float* __restrict__ cg, const float* __restrict__ Wfc,
                          const float* __restrict__ bfc, float* __restrict__ out)
{
    const int b = blockIdx.x, tid = threadIdx.x;   // 128 threads
    const float* f = g_feat + b * FEATC;
    float a0 = 0.0f, a1 = 0.0f;
    for (int i = tid; i < FEATC; i += 128) {
        float v = f[i];
        a0 = fmaf(v, Wfc[i], a0);
        a1 = fmaf(v, Wfc[FCIN_ + i], a1);
    }
    if (tid < 32) {
        float v = cg[b * 32 + tid];
        a0 = fmaf(v, Wfc[FEATC + tid], a0);
        a1 = fmaf(v, Wfc[FCIN_ + FEATC + tid], a1);
    }
#pragma unroll
    for (int o = 16; o > 0; o >>= 1) {
        a0 += __shfl_down_sync(0xffffffffu, a0, o);
        a1 += __shfl_down_sync(0xffffffffu, a1, o);
    }
    __shared__ float r0[4], r1[4];
    int w = tid >> 5, l = tid & 31;
    if (l == 0) { r0[w] = a0; r1[w] = a1; }
    __syncthreads();
    if (tid == 0) {
        out[b * 2 + 0] = r0[0] + r0[1] + r0[2] + r0[3] + bfc[0];
        out[b * 2 + 1] = r1[0] + r1[1] + r1[2] + r1[3] + bfc[1];
    }
}

// ---------------- kernel_launch ----------------
extern "C" void kernel_launch(void* const* d_in, const int* in_sizes, int n_in,
                              void* d_out, int out_size)
{
    (void)in_sizes; (void)n_in; (void)out_size;
    const float* current_game = (const float*)d_in[0];
    const float* games_home   = (const float*)d_in[1];
    const float* games_away   = (const float*)d_in[2];
    const float* games_vs     = (const float*)d_in[3];
    const float* players_home = (const float*)d_in[4];
    const float* players_away = (const float*)d_in[5];
    const float* Wih1 = (const float*)d_in[6];
    const float* Whh1 = (const float*)d_in[7];
    const float* bih1 = (const float*)d_in[8];
    const float* bhh1 = (const float*)d_in[9];
    const float* Wih2 = (const float*)d_in[10];
    const float* Whh2 = (const float*)d_in[11];
    const float* bih2 = (const float*)d_in[12];
    const float* bhh2 = (const float*)d_in[13];
    const float* Wih3 = (const float*)d_in[14];
    const float* Whh3 = (const float*)d_in[15];
    const float* bih3 = (const float*)d_in[16];
    const float* bhh3 = (const float*)d_in[17];
    const float* Wfc  = (const float*)d_in[18];
    const float* bfc  = (const float*)d_in[19];

    cudaFuncSetAttribute(lstm_merged, cudaFuncAttributeMaxDynamicSharedMemorySize, SMEM_MERGED);

    prep_kernel<<<1280, 256>>>(Wih1, Whh1, bih1, bhh1,
                               Wih2, Whh2, bih2, bhh2, bih3, bhh3);
    lstm_merged<<<480, 256, SMEM_MERGED>>>(games_home, games_away, games_vs,
                                           players_home, players_away, Wih3, Whh3);
    fc_kernel<<<512, 128>>>(current_game, Wfc, bfc, (float*)d_out);
}